// round 2
// baseline (speedup 1.0000x reference)
#include <cuda_runtime.h>
#include <math.h>

#define FULL_MASK 0xFFFFFFFFu

constexpr int MAXN = 65536;
constexpr int MAXE = 2097152;
constexpr int HID  = 32;
constexpr int MAXB = 64;
constexpr int NBLK = MAXN / 1024;

// ---- scratch (static __device__ globals; no runtime allocation) ----
__device__ int   g_cnt[MAXN];
__device__ int   g_rowoff[MAXN + 1];
__device__ int   g_cursor[MAXN];
__device__ int   g_blocksums[NBLK];
__device__ float g_dis[MAXN];
__device__ int   g_sorted[MAXE];
__device__ float g_bufA[MAXN * HID];   // "g" buffer (pre-aggregation, dis-scaled)
__device__ float g_bufB[MAXN * HID];   // "h" buffer (post-activation)
__device__ float g_pooled[MAXB * HID];

// ---------------------------------------------------------------------------
// init: zero degree counters and pooled accumulator
__global__ void __launch_bounds__(512) k_init(int n) {
    int i = blockIdx.x * blockDim.x + threadIdx.x;
    if (i < n) g_cnt[i] = 0;
    if (i < MAXB * HID) g_pooled[i] = 0.f;
}

// histogram of dst -> in-degree counts
__global__ void __launch_bounds__(512) k_hist(const int* __restrict__ dst, int e) {
    int i = blockIdx.x * blockDim.x + threadIdx.x;
    if (i < e) atomicAdd(&g_cnt[dst[i]], 1);
}

// per-1024 block exclusive scan of counts; block totals to g_blocksums.
// 512 threads, each owns 2 consecutive elements.
__global__ void __launch_bounds__(512) k_scan_block(int n) {
    __shared__ int wsum[16];
    int base = blockIdx.x * 1024;
    int t    = threadIdx.x;          // 0..511
    int lane = t & 31;
    int wid  = t >> 5;               // 0..15
    int i0 = base + t * 2;
    int c0 = (i0     < n) ? g_cnt[i0]     : 0;
    int c1 = (i0 + 1 < n) ? g_cnt[i0 + 1] : 0;
    int pair = c0 + c1;
    int v = pair;
    #pragma unroll
    for (int o = 1; o < 32; o <<= 1) {
        int u = __shfl_up_sync(FULL_MASK, v, o);
        if (lane >= o) v += u;
    }
    if (lane == 31) wsum[wid] = v;
    __syncthreads();
    if (wid == 0) {
        int s = (lane < 16) ? wsum[lane] : 0;
        #pragma unroll
        for (int o = 1; o < 16; o <<= 1) {
            int u = __shfl_up_sync(FULL_MASK, s, o);
            if (lane >= o) s += u;
        }
        if (lane < 16) wsum[lane] = s;
    }
    __syncthreads();
    int wbase = (wid > 0) ? wsum[wid - 1] : 0;
    int excl = wbase + v - pair;               // exclusive prefix of this pair
    if (i0     < n) g_rowoff[i0]     = excl;
    if (i0 + 1 < n) g_rowoff[i0 + 1] = excl + c0;
    if (t == 511) g_blocksums[blockIdx.x] = wsum[15];
}

// scan block sums (tiny) and write rowoff[n]
__global__ void __launch_bounds__(32) k_scan_top(int nblk, int n) {
    if (threadIdx.x == 0) {
        int run = 0;
        for (int b = 0; b < nblk; b++) {
            int t = g_blocksums[b];
            g_blocksums[b] = run;
            run += t;
        }
        g_rowoff[n] = run;   // == e
    }
}

// add block offsets, init cursors, compute dis = rsqrt(deg+1)
__global__ void __launch_bounds__(512) k_finalize(int n) {
    int i = blockIdx.x * blockDim.x + threadIdx.x;
    if (i < n) {
        int off = g_rowoff[i] + g_blocksums[i >> 10];
        g_rowoff[i] = off;
        g_cursor[i] = off;
        g_dis[i] = rsqrtf((float)(g_cnt[i] + 1));
    }
}

// scatter src into dst-sorted order
__global__ void __launch_bounds__(512) k_scatter(const int* __restrict__ src,
                                                 const int* __restrict__ dst, int e) {
    int i = blockIdx.x * blockDim.x + threadIdx.x;
    if (i < e) {
        int d = dst[i];
        int p = atomicAdd(&g_cursor[d], 1);
        g_sorted[p] = src[i];
    }
}

// ---------------------------------------------------------------------------
// GEMM + row scale: out[n][j] = (sum_k X[n][k]*W[j][k]) * dis[n]
// one warp per node, lane = output dim j
template <int K>
__global__ void __launch_bounds__(512) k_gemm_scale(const float* __restrict__ X,
                                                    const float* __restrict__ W,
                                                    float* __restrict__ out, int n) {
    int lane = threadIdx.x & 31;
    int node = (blockIdx.x * blockDim.x + threadIdx.x) >> 5;
    if (node >= n) return;
    float w[K];
    #pragma unroll
    for (int k = 0; k < K; k++) w[k] = W[lane * K + k];
    float xv = 0.f;
    if (K == 16) { if (lane < 16) xv = X[node * 16 + lane]; }
    else         { xv = X[node * 32 + lane]; }
    float a0 = 0.f, a1 = 0.f;
    #pragma unroll
    for (int k = 0; k < K; k += 2) {
        a0 += __shfl_sync(FULL_MASK, xv, k)     * w[k];
        a1 += __shfl_sync(FULL_MASK, xv, k + 1) * w[k + 1];
    }
    out[node * HID + lane] = (a0 + a1) * g_dis[node];
}

// ---------------------------------------------------------------------------
// aggregation: out[d] = tanh(dis[d]*(sum_{e in seg(d)} g[src_e] + g[d]) + b)
// warp per node, lane = dim; CTA covers 128 contiguous nodes (L1 locality)
__global__ void __launch_bounds__(512) k_agg(const float* __restrict__ gbuf,
                                             const float* __restrict__ bias,
                                             float* __restrict__ out, int n) {
    int lane = threadIdx.x & 31;
    int wid  = threadIdx.x >> 5;        // 0..15
    int base = blockIdx.x * 128;
    float b = bias[lane];
    #pragma unroll
    for (int it = 0; it < 8; it++) {
        int d = base + wid * 8 + it;
        if (d >= n) break;
        int start = g_rowoff[d];
        int end   = g_rowoff[d + 1];
        float acc = gbuf[d * HID + lane];   // self-loop term
        int p = start;
        while (p + 32 <= end) {
            int s = g_sorted[p + lane];
            float a0 = 0.f, a1 = 0.f, a2 = 0.f, a3 = 0.f;
            #pragma unroll
            for (int k = 0; k < 32; k += 4) {
                int s0 = __shfl_sync(FULL_MASK, s, k);
                int s1 = __shfl_sync(FULL_MASK, s, k + 1);
                int s2 = __shfl_sync(FULL_MASK, s, k + 2);
                int s3 = __shfl_sync(FULL_MASK, s, k + 3);
                a0 += gbuf[s0 * HID + lane];
                a1 += gbuf[s1 * HID + lane];
                a2 += gbuf[s2 * HID + lane];
                a3 += gbuf[s3 * HID + lane];
            }
            acc += (a0 + a1) + (a2 + a3);
            p += 32;
        }
        if (p < end) {
            int idx = p + lane;
            int s = (idx < end) ? g_sorted[idx] : 0;
            int m = end - p;
            for (int k = 0; k < m; k++) {
                int sk = __shfl_sync(FULL_MASK, s, k);
                acc += gbuf[sk * HID + lane];
            }
        }
        out[d * HID + lane] = tanhf(g_dis[d] * acc + b);
    }
}

// ---------------------------------------------------------------------------
// h3 = tanh(h @ Wl^T + bl); pooled[batch] += h3  (CTA per 1024-node chunk)
__global__ void __launch_bounds__(256) k_linpool(const float* __restrict__ hbuf,
                                                 const float* __restrict__ Wl,
                                                 const float* __restrict__ bl,
                                                 const int* __restrict__ vbatch,
                                                 int n, int nb) {
    __shared__ float pool[MAXB * HID];
    int tid  = threadIdx.x;
    int lane = tid & 31;
    int wid  = tid >> 5;
    int nwarp = blockDim.x >> 5;
    for (int i = tid; i < MAXB * HID; i += blockDim.x) pool[i] = 0.f;
    float w[32];
    #pragma unroll
    for (int k = 0; k < 32; k++) w[k] = Wl[lane * 32 + k];
    float b = bl[lane];
    __syncthreads();
    int base = blockIdx.x * 1024;
    int lim  = min(base + 1024, n);
    for (int nd = base + wid; nd < lim; nd += nwarp) {
        float hv = hbuf[nd * HID + lane];
        float a0 = b, a1 = 0.f;
        #pragma unroll
        for (int k = 0; k < 32; k += 2) {
            a0 += __shfl_sync(FULL_MASK, hv, k)     * w[k];
            a1 += __shfl_sync(FULL_MASK, hv, k + 1) * w[k + 1];
        }
        float v = tanhf(a0 + a1);
        int bb = vbatch[nd];
        atomicAdd(&pool[bb * HID + lane], v);
    }
    __syncthreads();
    for (int i = tid; i < nb * HID; i += blockDim.x) atomicAdd(&g_pooled[i], pool[i]);
}

// ---------------------------------------------------------------------------
// tiny head: post-pool linear, share_state MLP, comnet. One CTA, warp per row.
__global__ void __launch_bounds__(256) k_final(const float* __restrict__ share,
                        const float* __restrict__ Wp,  const float* __restrict__ bp,
                        const float* __restrict__ Vw1, const float* __restrict__ Vb1,
                        const float* __restrict__ Vw2, const float* __restrict__ Vb2,
                        const float* __restrict__ Vw3, const float* __restrict__ Vb3,
                        const float* __restrict__ Cw1, const float* __restrict__ Cb1,
                        const float* __restrict__ Cw2, const float* __restrict__ Cb2,
                        float* __restrict__ out, int nb) {
    int lane  = threadIdx.x & 31;
    int wid   = threadIdx.x >> 5;
    int nwarp = blockDim.x >> 5;
    for (int b = wid; b < nb; b += nwarp) {
        // post-pool linear: h1 = pooled @ Wp^T + bp
        float pv = g_pooled[b * HID + lane];
        float h1 = bp[lane];
        #pragma unroll
        for (int k = 0; k < 32; k++) h1 += __shfl_sync(FULL_MASK, pv, k) * Wp[lane * 32 + k];
        // MLP on share_state
        float s0 = share[b * 64 + lane];
        float s1 = share[b * 64 + 32 + lane];
        float t = Vb1[lane];
        #pragma unroll
        for (int k = 0; k < 32; k++) t += __shfl_sync(FULL_MASK, s0, k) * Vw1[lane * 64 + k];
        #pragma unroll
        for (int k = 0; k < 32; k++) t += __shfl_sync(FULL_MASK, s1, k) * Vw1[lane * 64 + 32 + k];
        t = tanhf(t);
        float t2 = Vb2[lane];
        #pragma unroll
        for (int k = 0; k < 32; k++) t2 += __shfl_sync(FULL_MASK, t, k) * Vw2[lane * 32 + k];
        t2 = tanhf(t2);
        float t3 = Vb3[lane];
        #pragma unroll
        for (int k = 0; k < 32; k++) t3 += __shfl_sync(FULL_MASK, t2, k) * Vw3[lane * 32 + k];
        // comnet
        float z = Cb1[lane];
        #pragma unroll
        for (int k = 0; k < 32; k++) z += __shfl_sync(FULL_MASK, h1, k) * Cw1[lane * 64 + k];
        #pragma unroll
        for (int k = 0; k < 32; k++) z += __shfl_sync(FULL_MASK, t3, k) * Cw1[lane * 64 + 32 + k];
        z = tanhf(z);
        float p = z * Cw2[lane];
        #pragma unroll
        for (int o = 16; o > 0; o >>= 1) p += __shfl_down_sync(FULL_MASK, p, o);
        if (lane == 0) out[b] = p + Cb2[0];
    }
}

// ---------------------------------------------------------------------------
extern "C" void kernel_launch(void* const* d_in, const int* in_sizes, int n_in,
                              void* d_out, int out_size) {
    const float* x      = (const float*)d_in[0];
    const int*   edge   = (const int*)  d_in[1];
    const int*   vbatch = (const int*)  d_in[2];
    const float* share  = (const float*)d_in[3];
    const float* W1 = (const float*)d_in[4];   const float* b1 = (const float*)d_in[5];
    const float* W2 = (const float*)d_in[6];   const float* b2 = (const float*)d_in[7];
    const float* Wl = (const float*)d_in[8];   const float* bl = (const float*)d_in[9];
    const float* Wp = (const float*)d_in[10];  const float* bp = (const float*)d_in[11];
    const float* Vw1 = (const float*)d_in[12]; const float* Vb1 = (const float*)d_in[13];
    const float* Vw2 = (const float*)d_in[14]; const float* Vb2 = (const float*)d_in[15];
    const float* Vw3 = (const float*)d_in[16]; const float* Vb3 = (const float*)d_in[17];
    const float* Cw1 = (const float*)d_in[18]; const float* Cb1 = (const float*)d_in[19];
    const float* Cw2 = (const float*)d_in[20]; const float* Cb2 = (const float*)d_in[21];

    const int n  = in_sizes[0] / 16;     // nodes
    const int e  = in_sizes[1] / 2;      // edges
    const int nb = in_sizes[3] / 64;     // graphs
    const int* src = edge;
    const int* dst = edge + e;
    float* out = (float*)d_out;

    const int nblk = (n + 1023) / 1024;

    // build dst-sorted edge list + dis
    k_init<<<(n + 511) / 512, 512>>>(n);
    k_hist<<<(e + 511) / 512, 512>>>(dst, e);
    k_scan_block<<<nblk, 512>>>(n);
    k_scan_top<<<1, 32>>>(nblk, n);
    k_finalize<<<(n + 511) / 512, 512>>>(n);
    k_scatter<<<(e + 511) / 512, 512>>>(src, dst, e);

    // conv1: g = (x @ W1^T)*dis ; h = tanh(dis*(seg_sum + self) + b1)
    k_gemm_scale<16><<<(n * 32 + 511) / 512, 512>>>(x, W1, g_bufA, n);
    k_agg<<<(n + 127) / 128, 512>>>(g_bufA, b1, g_bufB, n);

    // conv2
    k_gemm_scale<32><<<(n * 32 + 511) / 512, 512>>>(g_bufB, W2, g_bufA, n);
    k_agg<<<(n + 127) / 128, 512>>>(g_bufA, b2, g_bufB, n);

    // node linear + tanh + global_add_pool
    k_linpool<<<(n + 1023) / 1024, 256>>>(g_bufB, Wl, bl, vbatch, n, nb);

    // head
    k_final<<<1, 256>>>(share, Wp, bp, Vw1, Vb1, Vw2, Vb2, Vw3, Vb3,
                        Cw1, Cb1, Cw2, Cb2, out, nb);
}